// round 6
// baseline (speedup 1.0000x reference)
#include <cuda_runtime.h>
#include <math.h>
#include <stdint.h>

#define ENCD   1024
#define BATCH  32
#define SEQ    2048
#define MTOT   (BATCH * SEQ)   // 65536
#define NTILES 8               // 1024/128 n-tiles of the score GEMM
#define KC     16              // k per smem stage
#define NSTG   (ENCD / KC)     // 64 stages
#define NCHUNK 8               // k4 S-chunks

// Scratch (static device arrays: no allocation allowed).
__device__ float g_q[BATCH * ENCD];
__device__ float g_partials[NTILES * MTOT];
__device__ float g_attn[MTOT];
__device__ float g_ctx[NCHUNK][BATCH * ENCD];

// ---------------------------------------------------------------------------
__device__ __forceinline__ uint32_t f2tf32(float x) {
    uint32_t r; asm("cvt.rna.tf32.f32 %0, %1;" : "=r"(r) : "f"(x)); return r;
}
__device__ __forceinline__ void mma_tf32(float* d, const uint32_t* a, const uint32_t* b) {
    asm volatile(
        "mma.sync.aligned.m16n8k8.row.col.f32.tf32.tf32.f32 "
        "{%0,%1,%2,%3},{%4,%5,%6,%7},{%8,%9},{%0,%1,%2,%3};"
        : "+f"(d[0]), "+f"(d[1]), "+f"(d[2]), "+f"(d[3])
        : "r"(a[0]), "r"(a[1]), "r"(a[2]), "r"(a[3]), "r"(b[0]), "r"(b[1]));
}
__device__ __forceinline__ float tanh_fast(float x) {
    // tanh(x) = (e^2x-1)/(e^2x+1) via ex2/rcp approx; abs err ~1e-6.
    float xc = fminf(fmaxf(x, -9.0f), 9.0f);
    float y, r;
    asm("ex2.approx.f32 %0, %1;" : "=f"(y) : "f"(xc * 2.885390081777927f));
    asm("rcp.approx.f32 %0, %1;" : "=f"(r) : "f"(y + 1.0f));
    return (y - 1.0f) * r;
}

// Packed-stage geometry (float offsets).
// Per matrix: [buf(2)][kb(2)][row(128)][comp(8) + pad(4)]; kb stride has +8
// floats so comp+8*kb spans 16 distinct banks.
#define ROWST   12
#define KBST    (128 * ROWST + 8)   // 1544 floats (mod 32 == 8)
#define BUFST   (2 * KBST)          // 3088
#define MATSZ   (2 * BUFST)         // 6176 floats per matrix
#define OFF_A   0
#define OFF_B   MATSZ
#define OFF_QS  (2 * MATSZ)         // 12352
#define OFF_VS  (OFF_QS + 128)
#define OFF_SR  (OFF_VS + 128)      // 4 x 128 reduction
#define SMEMF   (OFF_SR + 512)      // 13120 floats
#define SM_TOTAL (SMEMF * 4)        // 52480 bytes (dynamic)

// ---------------------------------------------------------------------------
// K1: q'[b][e] = dec[b]@w2 + b2 + b1
// ---------------------------------------------------------------------------
__global__ __launch_bounds__(256)
void k1_query(const float* __restrict__ dec, const float* __restrict__ w2,
              const float* __restrict__ b1, const float* __restrict__ b2) {
    __shared__ float sdec[ENCD];
    const int b = blockIdx.x;
    for (int i = threadIdx.x; i < ENCD; i += 256) sdec[i] = dec[b * ENCD + i];
    __syncthreads();
    float acc[4] = {0.f, 0.f, 0.f, 0.f};
    const int e0 = threadIdx.x;
    for (int d = 0; d < ENCD; d++) {
        const float dv = sdec[d];
        const float* wrow = w2 + (size_t)d * ENCD;
        #pragma unroll
        for (int c = 0; c < 4; c++) acc[c] += dv * wrow[e0 + 256 * c];
    }
    #pragma unroll
    for (int c = 0; c < 4; c++) {
        const int e = e0 + 256 * c;
        g_q[b * ENCD + e] = acc[c] + b1[e] + b2[e];
    }
}

// ---------------------------------------------------------------------------
// K2: fused score GEMM, mma.sync tf32, pair-packed conflict-free smem.
// CTA tile 128x128, K=1024 in 64 double-buffered KC=16 stages.
// 8 warps: 2(M) x 4(N), warp tile 64x32 via 4x4 m16n8k8.
// grid (512, 8), 256 threads. Warps 0-3 produce A, 4-7 produce B.
// ---------------------------------------------------------------------------
__global__ __launch_bounds__(256, 2)
void k2_scores(const float* __restrict__ enc, const float* __restrict__ w1,
               const float* __restrict__ v) {
    extern __shared__ __align__(16) float sm[];
    float* sA = sm + OFF_A;
    float* sB = sm + OFF_B;
    float* qs = sm + OFF_QS;
    float* vs = sm + OFF_VS;
    float* sred = sm + OFF_SR;

    const int m0 = blockIdx.x * 128;
    const int nt = blockIdx.y, n0 = nt * 128;
    const int b  = m0 / SEQ;
    const int t  = threadIdx.x;
    const int lane = t & 31, w = t >> 5;
    const int wm = w & 1, wn = w >> 1;
    const int g = lane >> 2, c = lane & 3;

    if (t < 128) { qs[t] = g_q[b * ENCD + n0 + t]; vs[t] = v[n0 + t]; }

    // Producer indexing.
    const bool isA = (t < 128);
    const float4* encv = (const float4*)(enc + (size_t)m0 * ENCD);
    const float4* w1v  = (const float4*)w1;
    const int u  = t & 127;
    // A: row m = u, 4 float4/stage -> 2 kb x 2 STS.128.
    // B: k = u&15, nh = u>>4 (0..7); 4 float4 at n = nh*4 + 32*j.
    const int bk = u & 15, bnh = u >> 4;
    const int bkb = bk >> 3, bcomp = ((bk & 3) << 1) | ((bk >> 2) & 1);
    const int n0_4 = n0 >> 2;

    float acc[4][4][4];
    #pragma unroll
    for (int mi = 0; mi < 4; mi++)
        #pragma unroll
        for (int ni = 0; ni < 4; ni++)
            #pragma unroll
            for (int r = 0; r < 4; r++) acc[mi][ni][r] = 0.f;

    float4 pf[4];   // producer LDG buffer for next stage

    // ---- producer helpers (inlined via lambdas-by-macro style) ----
    #define LDG_STAGE(s)                                                        \
        do {                                                                    \
            if (isA) {                                                          \
                const float4* src = encv + (size_t)u * 256 + (s) * 4;           \
                pf[0] = src[0]; pf[1] = src[1]; pf[2] = src[2]; pf[3] = src[3]; \
            } else {                                                            \
                const size_t kr = ((size_t)((s) * KC + bk)) * 256 + n0_4;       \
                pf[0] = w1v[kr + bnh];      pf[1] = w1v[kr + bnh + 8];          \
                pf[2] = w1v[kr + bnh + 16]; pf[3] = w1v[kr + bnh + 24];         \
            }                                                                   \
        } while (0)

    #define STS_STAGE(buf)                                                      \
        do {                                                                    \
            if (isA) {                                                          \
                _Pragma("unroll")                                               \
                for (int kb = 0; kb < 2; kb++) {                                \
                    float4 f0 = pf[kb * 2], f1 = pf[kb * 2 + 1];                \
                    uint32_t* dst = (uint32_t*)(sA + (buf) * BUFST + kb * KBST  \
                                                + u * ROWST);                   \
                    uint4 lo = make_uint4(f2tf32(f0.x), f2tf32(f1.x),           \
                                          f2tf32(f0.y), f2tf32(f1.y));          \
                    uint4 hi = make_uint4(f2tf32(f0.z), f2tf32(f1.z),           \
                                          f2tf32(f0.w), f2tf32(f1.w));          \
                    *(uint4*)(dst)     = lo;                                    \
                    *(uint4*)(dst + 4) = hi;                                    \
                }                                                               \
            } else {                                                            \
                uint32_t* base = (uint32_t*)(sB + (buf) * BUFST + bkb * KBST);  \
                _Pragma("unroll")                                               \
                for (int j = 0; j < 4; j++) {                                   \
                    const int nbase = bnh * 4 + 32 * j;                         \
                    base[(nbase + 0) * ROWST + bcomp] = f2tf32(pf[j].x);        \
                    base[(nbase + 1) * ROWST + bcomp] = f2tf32(pf[j].y);        \
                    base[(nbase + 2) * ROWST + bcomp] = f2tf32(pf[j].z);        \
                    base[(nbase + 3) * ROWST + bcomp] = f2tf32(pf[j].w);        \
                }                                                               \
            }                                                                   \
        } while (0)

    // Prologue: stage 0.
    LDG_STAGE(0);
    STS_STAGE(0);
    __syncthreads();

    for (int s = 0; s < NSTG; s++) {
        const int buf = s & 1;
        if (s < NSTG - 1) LDG_STAGE(s + 1);

        // Consume stage s: 2 K=8 steps.
        const float* aB = sA + buf * BUFST;
        const float* bB = sB + buf * BUFST;
        #pragma unroll
        for (int kb = 0; kb < 2; kb++) {
            const float* aK = aB + kb * KBST;
            const float* bK = bB + kb * KBST;
            uint32_t af[4][4], bf[4][2];
            #pragma unroll
            for (int mi = 0; mi < 4; mi++) {
                const int M = wm * 64 + mi * 16 + g;
                float2 p = *(const float2*)(aK + M * ROWST + c * 2);
                float2 q = *(const float2*)(aK + (M + 8) * ROWST + c * 2);
                af[mi][0] = __float_as_uint(p.x);  // A[g][c]
                af[mi][1] = __float_as_uint(q.x);  // A[g+8][c]
                af[mi][2] = __float_as_uint(p.y);  // A[g][c+4]
                af[mi][3] = __float_as_uint(q.y);  // A[g+8][c+4]
            }
            #pragma unroll
            for (int ni = 0; ni < 4; ni++) {
                const int N = wn * 32 + ni * 8 + g;
                float2 p = *(const float2*)(bK + N * ROWST + c * 2);
                bf[ni][0] = __float_as_uint(p.x);  // B[c][n]
                bf[ni][1] = __float_as_uint(p.y);  // B[c+4][n]
            }
            #pragma unroll
            for (int mi = 0; mi < 4; mi++)
                #pragma unroll
                for (int ni = 0; ni < 4; ni++)
                    mma_tf32(acc[mi][ni], af[mi], bf[ni]);
        }

        if (s < NSTG - 1) STS_STAGE(buf ^ 1);
        __syncthreads();
    }

    // Epilogue. C frag: c0=(g,2c), c1=(g,2c+1), c2=(g+8,2c), c3=(g+8,2c+1).
    float rs0[4], rs1[4];
    #pragma unroll
    for (int mi = 0; mi < 4; mi++) {
        float s0 = 0.f, s1 = 0.f;
        #pragma unroll
        for (int ni = 0; ni < 4; ni++) {
            const int n_ = wn * 32 + ni * 8 + c * 2;
            const float q0 = qs[n_], q1 = qs[n_ + 1];
            const float v0 = vs[n_], v1 = vs[n_ + 1];
            s0 += tanh_fast(acc[mi][ni][0] + q0) * v0
                + tanh_fast(acc[mi][ni][1] + q1) * v1;
            s1 += tanh_fast(acc[mi][ni][2] + q0) * v0
                + tanh_fast(acc[mi][ni][3] + q1) * v1;
        }
        s0 += __shfl_xor_sync(0xffffffffu, s0, 1);
        s0 += __shfl_xor_sync(0xffffffffu, s0, 2);
        s1 += __shfl_xor_sync(0xffffffffu, s1, 1);
        s1 += __shfl_xor_sync(0xffffffffu, s1, 2);
        rs0[mi] = s0; rs1[mi] = s1;
    }
    if (c == 0) {
        #pragma unroll
        for (int mi = 0; mi < 4; mi++) {
            sred[wn * 128 + wm * 64 + mi * 16 + g]     = rs0[mi];
            sred[wn * 128 + wm * 64 + mi * 16 + g + 8] = rs1[mi];
        }
    }
    __syncthreads();
    if (t < 128)
        g_partials[(size_t)nt * MTOT + m0 + t] =
            (sred[t] + sred[128 + t]) + (sred[256 + t] + sred[384 + t]);
}

// ---------------------------------------------------------------------------
// K3: sum NTILES partials (fixed order), softmax over S per batch.
// ---------------------------------------------------------------------------
__global__ __launch_bounds__(256)
void k3_softmax() {
    __shared__ float red[256];
    const int b = blockIdx.x, t = threadIdx.x;
    float sc[8];
    float mx = -1e30f;
    #pragma unroll
    for (int i = 0; i < 8; i++) {
        const int s = t + 256 * i;
        float v0 = 0.f;
        #pragma unroll
        for (int nt = 0; nt < NTILES; nt++)
            v0 += g_partials[(size_t)nt * MTOT + b * SEQ + s];
        sc[i] = v0;
        mx = fmaxf(mx, v0);
    }
    red[t] = mx; __syncthreads();
    for (int o = 128; o > 0; o >>= 1) {
        if (t < o) red[t] = fmaxf(red[t], red[t + o]);
        __syncthreads();
    }
    mx = red[0]; __syncthreads();
    float sum = 0.f;
    #pragma unroll
    for (int i = 0; i < 8; i++) { sc[i] = expf(sc[i] - mx); sum += sc[i]; }
    red[t] = sum; __syncthreads();
    for (int o = 128; o > 0; o >>= 1) {
        if (t < o) red[t] += red[t + o];
        __syncthreads();
    }
    const float inv = 1.f / red[0];
    #pragma unroll
    for (int i = 0; i < 8; i++)
        g_attn[b * SEQ + t + 256 * i] = sc[i] * inv;
}

// ---------------------------------------------------------------------------
// K4: partial context over S-chunks of 256. grid (4, 32, 8), 256 thr.
// ---------------------------------------------------------------------------
__global__ __launch_bounds__(256)
void k4_context(const float* __restrict__ enc) {
    __shared__ float sat[256];
    const int b  = blockIdx.y;
    const int sc = blockIdx.z;
    const int e  = blockIdx.x * 256 + threadIdx.x;
    const int sbase = sc * 256;
    sat[threadIdx.x] = g_attn[b * SEQ + sbase + threadIdx.x];
    __syncthreads();
    const float* ep = enc + ((size_t)b * SEQ + sbase) * ENCD + e;
    float a0 = 0, a1 = 0, a2 = 0, a3 = 0, a4 = 0, a5 = 0, a6 = 0, a7 = 0;
    for (int s = 0; s < 256; s += 8) {
        a0 += sat[s + 0] * ep[(size_t)(s + 0) * ENCD];
        a1 += sat[s + 1] * ep[(size_t)(s + 1) * ENCD];
        a2 += sat[s + 2] * ep[(size_t)(s + 2) * ENCD];
        a3 += sat[s + 3] * ep[(size_t)(s + 3) * ENCD];
        a4 += sat[s + 4] * ep[(size_t)(s + 4) * ENCD];
        a5 += sat[s + 5] * ep[(size_t)(s + 5) * ENCD];
        a6 += sat[s + 6] * ep[(size_t)(s + 6) * ENCD];
        a7 += sat[s + 7] * ep[(size_t)(s + 7) * ENCD];
    }
    g_ctx[sc][b * ENCD + e] = ((a0 + a1) + (a2 + a3)) + ((a4 + a5) + (a6 + a7));
}

__global__ __launch_bounds__(256)
void k5_reduce(float* __restrict__ out) {
    const int i = blockIdx.x * 256 + threadIdx.x;
    float s = 0.f;
    #pragma unroll
    for (int ch = 0; ch < NCHUNK; ch++) s += g_ctx[ch][i];
    out[i] = s;
}

// ---------------------------------------------------------------------------
extern "C" void kernel_launch(void* const* d_in, const int* in_sizes, int n_in,
                              void* d_out, int out_size) {
    const float* enc = (const float*)d_in[0];
    const float* dec = (const float*)d_in[1];
    const float* w1  = (const float*)d_in[2];
    const float* b1  = (const float*)d_in[3];
    const float* w2  = (const float*)d_in[4];
    const float* b2  = (const float*)d_in[5];
    const float* v   = (const float*)d_in[6];
    float* out = (float*)d_out;

    cudaFuncSetAttribute(k2_scores, cudaFuncAttributeMaxDynamicSharedMemorySize,
                         SM_TOTAL);

    k1_query<<<32, 256>>>(dec, w2, b1, b2);
    k2_scores<<<dim3(512, NTILES), 256, SM_TOTAL>>>(enc, w1, v);
    k3_softmax<<<32, 256>>>();
    k4_context<<<dim3(4, 32, NCHUNK), 256>>>(enc);
    k5_reduce<<<128, 256>>>(out);
}

// round 7
// speedup vs baseline: 1.7252x; 1.7252x over previous
#include <cuda_runtime.h>
#include <math.h>
#include <stdint.h>

#define ENCD   1024
#define BATCH  32
#define SEQ    2048
#define MTOT   (BATCH * SEQ)   // 65536
#define NTILES 8               // 1024/128 column tiles of the score GEMM
#define KS     16              // k-chunk per smem stage
#define NCHUNK 8               // k4 S-chunks

// Scratch (static device arrays: no allocation allowed).
__device__ float g_q[BATCH * ENCD];            // q'[b][e] = dec@w2 + b2 + b1
__device__ float g_partials[NTILES * MTOT];    // per-ntile partial scores
__device__ float g_attn[MTOT];                 // softmax weights
__device__ float g_ctx[NCHUNK][BATCH * ENCD];  // k4 s-chunk partial contexts

// ---------------------------------------------------------------------------
__device__ __forceinline__ uint32_t f2tf32(float x) {
    uint32_t r; asm("cvt.rna.tf32.f32 %0, %1;" : "=r"(r) : "f"(x)); return r;
}
__device__ __forceinline__ void mma_tf32(float* d, const uint32_t* a, const uint32_t* b) {
    asm volatile(
        "mma.sync.aligned.m16n8k8.row.col.f32.tf32.tf32.f32 "
        "{%0,%1,%2,%3},{%4,%5,%6,%7},{%8,%9},{%0,%1,%2,%3};"
        : "+f"(d[0]), "+f"(d[1]), "+f"(d[2]), "+f"(d[3])
        : "r"(a[0]), "r"(a[1]), "r"(a[2]), "r"(a[3]), "r"(b[0]), "r"(b[1]));
}
__device__ __forceinline__ float tanh_fast(float x) {
    // tanh(x) = (e^2x-1)/(e^2x+1) via ex2/rcp approx; abs err ~1e-6.
    float xc = fminf(fmaxf(x, -9.0f), 9.0f);
    float y, r;
    asm("ex2.approx.f32 %0, %1;" : "=f"(y) : "f"(xc * 2.885390081777927f));
    asm("rcp.approx.f32 %0, %1;" : "=f"(r) : "f"(y + 1.0f));
    return (y - 1.0f) * r;
}

// ---------------------------------------------------------------------------
// K1: q'[b][e] = dec[b]@w2 + b2 + b1
// ---------------------------------------------------------------------------
__global__ __launch_bounds__(256)
void k1_query(const float* __restrict__ dec, const float* __restrict__ w2,
              const float* __restrict__ b1, const float* __restrict__ b2) {
    __shared__ float sdec[ENCD];
    const int b = blockIdx.x;
    for (int i = threadIdx.x; i < ENCD; i += 256) sdec[i] = dec[b * ENCD + i];
    __syncthreads();
    float acc[4] = {0.f, 0.f, 0.f, 0.f};
    const int e0 = threadIdx.x;
    for (int d = 0; d < ENCD; d++) {
        const float dv = sdec[d];
        const float* wrow = w2 + (size_t)d * ENCD;
        #pragma unroll
        for (int c = 0; c < 4; c++) acc[c] += dv * wrow[e0 + 256 * c];
    }
    #pragma unroll
    for (int c = 0; c < 4; c++) {
        const int e = e0 + 256 * c;
        g_q[b * ENCD + e] = acc[c] + b1[e] + b2[e];
    }
}

// ---------------------------------------------------------------------------
// K2: fused score GEMM on tf32 mma.sync (R3 structure).
//   C-tile 128x128, K=1024, double-buffered smem, 8 warps 2(M)x4(N),
//   warp 64x32 via 4x4 m16n8k8. Epilogue: tanh_fast + v-dot, quad shuffle,
//   per-ntile partial out. grid (8, 512): 8 n-tiles of one m-tile adjacent
//   so enc m-rows are read from DRAM once (L2-shared across n-tiles).
// ---------------------------------------------------------------------------
__global__ __launch_bounds__(256, 2)
void k2_scores(const float* __restrict__ enc, const float* __restrict__ w1,
               const float* __restrict__ v) {
    __shared__ uint32_t As[2][KS][136];   // A^T (k-major), +8 pad
    __shared__ uint32_t Bs[2][KS][136];   // B   (k-major), +8 pad
    __shared__ float qs[128], vs[128];
    __shared__ float sredN[4][128];

    const int nt = blockIdx.x, n0 = nt * 128;
    const int m0 = blockIdx.y * 128;
    const int b  = m0 / SEQ;              // SEQ % 128 == 0
    const int t  = threadIdx.x;
    const int lane = t & 31, w = t >> 5;
    const int wm = w & 1, wn = w >> 1;    // warp grid 2 x 4
    const int g = lane >> 2, c = lane & 3;

    if (t < 128) { qs[t] = g_q[b * ENCD + n0 + t]; vs[t] = v[n0 + t]; }

    // A stage loads: 128 rows x 16 k = 512 float4, 2/thread.
    const int arow0 = t >> 2, akp = t & 3;
    const int arow1 = (t + 256) >> 2;
    const float4* encv = (const float4*)(enc + (size_t)m0 * ENCD);
    // B stage loads: 16 rows x 128 = 512 float4, 2/thread (coalesced).
    const int bkr0 = t >> 5, bnv = t & 31, bkr1 = bkr0 + 8;
    const float4* w1v = (const float4*)w1;
    const int ncol4 = (n0 >> 2) + bnv;

    float acc[4][4][4];
    #pragma unroll
    for (int mi = 0; mi < 4; mi++)
        #pragma unroll
        for (int ni = 0; ni < 4; ni++)
            #pragma unroll
            for (int r = 0; r < 4; r++) acc[mi][ni][r] = 0.f;

    // Prologue: stage 0 (k0 = 0)
    {
        float4 ra0 = encv[arow0 * 256 + akp];
        float4 ra1 = encv[arow1 * 256 + akp];
        float4 rb0 = w1v[(size_t)bkr0 * 256 + ncol4];
        float4 rb1 = w1v[(size_t)bkr1 * 256 + ncol4];
        As[0][akp * 4 + 0][arow0] = f2tf32(ra0.x);
        As[0][akp * 4 + 1][arow0] = f2tf32(ra0.y);
        As[0][akp * 4 + 2][arow0] = f2tf32(ra0.z);
        As[0][akp * 4 + 3][arow0] = f2tf32(ra0.w);
        As[0][akp * 4 + 0][arow1] = f2tf32(ra1.x);
        As[0][akp * 4 + 1][arow1] = f2tf32(ra1.y);
        As[0][akp * 4 + 2][arow1] = f2tf32(ra1.z);
        As[0][akp * 4 + 3][arow1] = f2tf32(ra1.w);
        uint4 ub0 = make_uint4(f2tf32(rb0.x), f2tf32(rb0.y), f2tf32(rb0.z), f2tf32(rb0.w));
        uint4 ub1 = make_uint4(f2tf32(rb1.x), f2tf32(rb1.y), f2tf32(rb1.z), f2tf32(rb1.w));
        *(uint4*)&Bs[0][bkr0][bnv * 4] = ub0;
        *(uint4*)&Bs[0][bkr1][bnv * 4] = ub1;
    }
    __syncthreads();

    for (int ks = 0; ks < 64; ks++) {
        const int cur = ks & 1, nxt = cur ^ 1;
        float4 ra0, ra1, rb0, rb1;
        if (ks < 63) {
            const int k0 = (ks + 1) * KS;
            ra0 = encv[arow0 * 256 + (k0 >> 2) + akp];
            ra1 = encv[arow1 * 256 + (k0 >> 2) + akp];
            rb0 = w1v[(size_t)(k0 + bkr0) * 256 + ncol4];
            rb1 = w1v[(size_t)(k0 + bkr1) * 256 + ncol4];
        }
        #pragma unroll
        for (int kk = 0; kk < KS; kk += 8) {
            uint32_t af[4][4], bf[4][2];
            #pragma unroll
            for (int mi = 0; mi < 4; mi++) {
                const int mb = wm * 64 + mi * 16 + g;
                af[mi][0] = As[cur][kk + c][mb];
                af[mi][1] = As[cur][kk + c][mb + 8];
                af[mi][2] = As[cur][kk + c + 4][mb];
                af[mi][3] = As[cur][kk + c + 4][mb + 8];
            }
            #pragma unroll
            for (int ni = 0; ni < 4; ni++) {
                const int nb = wn * 32 + ni * 8 + g;
                bf[ni][0] = Bs[cur][kk + c][nb];
                bf[ni][1] = Bs[cur][kk + c + 4][nb];
            }
            #pragma unroll
            for (int mi = 0; mi < 4; mi++)
                #pragma unroll
                for (int ni = 0; ni < 4; ni++)
                    mma_tf32(acc[mi][ni], af[mi], bf[ni]);
        }
        if (ks < 63) {
            As[nxt][akp * 4 + 0][arow0] = f2tf32(ra0.x);
            As[nxt][akp * 4 + 1][arow0] = f2tf32(ra0.y);
            As[nxt][akp * 4 + 2][arow0] = f2tf32(ra0.z);
            As[nxt][akp * 4 + 3][arow0] = f2tf32(ra0.w);
            As[nxt][akp * 4 + 0][arow1] = f2tf32(ra1.x);
            As[nxt][akp * 4 + 1][arow1] = f2tf32(ra1.y);
            As[nxt][akp * 4 + 2][arow1] = f2tf32(ra1.z);
            As[nxt][akp * 4 + 3][arow1] = f2tf32(ra1.w);
            uint4 ub0 = make_uint4(f2tf32(rb0.x), f2tf32(rb0.y), f2tf32(rb0.z), f2tf32(rb0.w));
            uint4 ub1 = make_uint4(f2tf32(rb1.x), f2tf32(rb1.y), f2tf32(rb1.z), f2tf32(rb1.w));
            *(uint4*)&Bs[nxt][bkr0][bnv * 4] = ub0;
            *(uint4*)&Bs[nxt][bkr1][bnv * 4] = ub1;
            __syncthreads();
        }
    }

    // Epilogue. C frag: c0=(g,2c), c1=(g,2c+1), c2=(g+8,2c), c3=(g+8,2c+1)
    float rs0[4], rs1[4];
    #pragma unroll
    for (int mi = 0; mi < 4; mi++) {
        float s0 = 0.f, s1 = 0.f;
        #pragma unroll
        for (int ni = 0; ni < 4; ni++) {
            const int n_ = wn * 32 + ni * 8 + c * 2;
            const float q0 = qs[n_], q1 = qs[n_ + 1];
            const float v0 = vs[n_], v1 = vs[n_ + 1];
            s0 += tanh_fast(acc[mi][ni][0] + q0) * v0
                + tanh_fast(acc[mi][ni][1] + q1) * v1;
            s1 += tanh_fast(acc[mi][ni][2] + q0) * v0
                + tanh_fast(acc[mi][ni][3] + q1) * v1;
        }
        s0 += __shfl_xor_sync(0xffffffffu, s0, 1);
        s0 += __shfl_xor_sync(0xffffffffu, s0, 2);
        s1 += __shfl_xor_sync(0xffffffffu, s1, 1);
        s1 += __shfl_xor_sync(0xffffffffu, s1, 2);
        rs0[mi] = s0; rs1[mi] = s1;
    }
    if (c == 0) {
        #pragma unroll
        for (int mi = 0; mi < 4; mi++) {
            sredN[wn][wm * 64 + mi * 16 + g]     = rs0[mi];
            sredN[wn][wm * 64 + mi * 16 + g + 8] = rs1[mi];
        }
    }
    __syncthreads();
    if (t < 128)
        g_partials[(size_t)nt * MTOT + m0 + t] =
            (sredN[0][t] + sredN[1][t]) + (sredN[2][t] + sredN[3][t]);
}

// ---------------------------------------------------------------------------
// K3: sum 8 partials (fixed order -> deterministic), softmax over S per batch.
// ---------------------------------------------------------------------------
__global__ __launch_bounds__(256)
void k3_softmax() {
    __shared__ float red[256];
    const int b = blockIdx.x, t = threadIdx.x;
    float sc[8];
    float mx = -1e30f;
    #pragma unroll
    for (int i = 0; i < 8; i++) {
        const int s = t + 256 * i;
        float v0 = 0.f;
        #pragma unroll
        for (int nt = 0; nt < NTILES; nt++)
            v0 += g_partials[(size_t)nt * MTOT + b * SEQ + s];
        sc[i] = v0;
        mx = fmaxf(mx, v0);
    }
    red[t] = mx; __syncthreads();
    for (int o = 128; o > 0; o >>= 1) {
        if (t < o) red[t] = fmaxf(red[t], red[t + o]);
        __syncthreads();
    }
    mx = red[0]; __syncthreads();
    float sum = 0.f;
    #pragma unroll
    for (int i = 0; i < 8; i++) { sc[i] = expf(sc[i] - mx); sum += sc[i]; }
    red[t] = sum; __syncthreads();
    for (int o = 128; o > 0; o >>= 1) {
        if (t < o) red[t] += red[t + o];
        __syncthreads();
    }
    const float inv = 1.f / red[0];
    #pragma unroll
    for (int i = 0; i < 8; i++)
        g_attn[b * SEQ + t + 256 * i] = sc[i] * inv;
}

// ---------------------------------------------------------------------------
// K4: partial context over S-chunks of 256. grid (4, 32, 8), 256 thr.
// ---------------------------------------------------------------------------
__global__ __launch_bounds__(256)
void k4_context(const float* __restrict__ enc) {
    __shared__ float sat[256];
    const int b  = blockIdx.y;
    const int sc = blockIdx.z;
    const int e  = blockIdx.x * 256 + threadIdx.x;
    const int sbase = sc * 256;
    sat[threadIdx.x] = g_attn[b * SEQ + sbase + threadIdx.x];
    __syncthreads();
    const float* ep = enc + ((size_t)b * SEQ + sbase) * ENCD + e;
    float a0 = 0, a1 = 0, a2 = 0, a3 = 0, a4 = 0, a5 = 0, a6 = 0, a7 = 0;
    for (int s = 0; s < 256; s += 8) {
        a0 += sat[s + 0] * ep[(size_t)(s + 0) * ENCD];
        a1 += sat[s + 1] * ep[(size_t)(s + 1) * ENCD];
        a2 += sat[s + 2] * ep[(size_t)(s + 2) * ENCD];
        a3 += sat[s + 3] * ep[(size_t)(s + 3) * ENCD];
        a4 += sat[s + 4] * ep[(size_t)(s + 4) * ENCD];
        a5 += sat[s + 5] * ep[(size_t)(s + 5) * ENCD];
        a6 += sat[s + 6] * ep[(size_t)(s + 6) * ENCD];
        a7 += sat[s + 7] * ep[(size_t)(s + 7) * ENCD];
    }
    g_ctx[sc][b * ENCD + e] = ((a0 + a1) + (a2 + a3)) + ((a4 + a5) + (a6 + a7));
}

__global__ __launch_bounds__(256)
void k5_reduce(float* __restrict__ out) {
    const int i = blockIdx.x * 256 + threadIdx.x;
    float s = 0.f;
    #pragma unroll
    for (int ch = 0; ch < NCHUNK; ch++) s += g_ctx[ch][i];
    out[i] = s;
}

// ---------------------------------------------------------------------------
extern "C" void kernel_launch(void* const* d_in, const int* in_sizes, int n_in,
                              void* d_out, int out_size) {
    const float* enc = (const float*)d_in[0];   // [32, 2048, 1024]
    const float* dec = (const float*)d_in[1];   // [32, 1, 1024]
    const float* w1  = (const float*)d_in[2];   // [1024, 1024]
    const float* b1  = (const float*)d_in[3];   // [1024]
    const float* w2  = (const float*)d_in[4];   // [1024, 1024]
    const float* b2  = (const float*)d_in[5];   // [1024]
    const float* v   = (const float*)d_in[6];   // [1024, 1]
    // d_in[7] = bv cancels in softmax.
    float* out = (float*)d_out;                 // [32, 1024] fp32

    k1_query<<<32, 256>>>(dec, w2, b1, b2);
    k2_scores<<<dim3(NTILES, 512), 256>>>(enc, w1, v);
    k3_softmax<<<32, 256>>>();
    k4_context<<<dim3(4, 32, NCHUNK), 256>>>(enc);
    k5_reduce<<<128, 256>>>(out);
}

// round 8
// speedup vs baseline: 2.1752x; 1.2608x over previous
#include <cuda_runtime.h>
#include <math.h>
#include <stdint.h>

#define ENCD   1024
#define BATCH  32
#define SEQ    2048
#define MTOT   (BATCH * SEQ)   // 65536
#define NTILES 8               // 1024/128 n-tiles
#define NSTG   64              // K stages of 16
#define NCHUNK 8               // k4 S-chunks

// Scratch (static device arrays: no allocation allowed).
__device__ float g_q[BATCH * ENCD];
__device__ float g_partials[NTILES * MTOT];
__device__ float g_attn[MTOT];
__device__ float g_ctx[NCHUNK][BATCH * ENCD];

// ---------------------------------------------------------------------------
__device__ __forceinline__ void mma_tf32(float* d, const uint32_t* a, const uint32_t* b) {
    asm volatile(
        "mma.sync.aligned.m16n8k8.row.col.f32.tf32.tf32.f32 "
        "{%0,%1,%2,%3},{%4,%5,%6,%7},{%8,%9},{%0,%1,%2,%3};"
        : "+f"(d[0]), "+f"(d[1]), "+f"(d[2]), "+f"(d[3])
        : "r"(a[0]), "r"(a[1]), "r"(a[2]), "r"(a[3]), "r"(b[0]), "r"(b[1]));
}
__device__ __forceinline__ float tanh_fast(float x) {
    float xc = fminf(fmaxf(x, -9.0f), 9.0f);
    float y, r;
    asm("ex2.approx.f32 %0, %1;" : "=f"(y) : "f"(xc * 2.885390081777927f));
    asm("rcp.approx.f32 %0, %1;" : "=f"(r) : "f"(y + 1.0f));
    return (y - 1.0f) * r;
}
__device__ __forceinline__ uint32_t smem_u32(const void* p) {
    uint32_t a;
    asm("{ .reg .u64 t; cvta.to.shared.u64 t, %1; cvt.u32.u64 %0, t; }"
        : "=r"(a) : "l"(p));
    return a;
}
#define CP_ASYNC16(dst, src) \
    asm volatile("cp.async.cg.shared.global [%0], [%1], 16;" :: "r"(dst), "l"(src) : "memory")
#define CP_COMMIT()  asm volatile("cp.async.commit_group;" ::: "memory")
#define CP_WAIT2()   asm volatile("cp.async.wait_group 2;" ::: "memory")

// smem geometry (bytes). A stage: 128 rows x 20 floats (16 data + 4 pad).
// B stage: 16 rows x 136 floats (128 data + 8 pad). 4-stage ring.
#define ASTG   10240
#define BSTG   8704
#define OFF_A  0
#define OFF_B  (4 * ASTG)            // 40960
#define OFF_QS (OFF_B + 4 * BSTG)    // 75776
#define OFF_VS (OFF_QS + 512)
#define OFF_SR (OFF_VS + 512)
#define SMTOT  (OFF_SR + 2048)       // 78848

// ---------------------------------------------------------------------------
// K1: q'[b][e] = dec[b]@w2 + b2 + b1
// ---------------------------------------------------------------------------
__global__ __launch_bounds__(256)
void k1_query(const float* __restrict__ dec, const float* __restrict__ w2,
              const float* __restrict__ b1, const float* __restrict__ b2) {
    __shared__ float sdec[ENCD];
    const int b = blockIdx.x;
    for (int i = threadIdx.x; i < ENCD; i += 256) sdec[i] = dec[b * ENCD + i];
    __syncthreads();
    float acc[4] = {0.f, 0.f, 0.f, 0.f};
    const int e0 = threadIdx.x;
    for (int d = 0; d < ENCD; d++) {
        const float dv = sdec[d];
        const float* wrow = w2 + (size_t)d * ENCD;
        #pragma unroll
        for (int c = 0; c < 4; c++) acc[c] += dv * wrow[e0 + 256 * c];
    }
    #pragma unroll
    for (int c = 0; c < 4; c++) {
        const int e = e0 + 256 * c;
        g_q[b * ENCD + e] = acc[c] + b1[e] + b2[e];
    }
}

// ---------------------------------------------------------------------------
// K2: fused score GEMM, tf32 mma.sync, cp.async 4-stage pipeline.
// CTA tile 128x128, 8 warps 2(M)x4(N), warp 64x32 via 4x4 m16n8k8.
// No cvt: HMMA.TF32 truncates fp32 operands in HW.
// grid (8, 512), 256 threads.
// ---------------------------------------------------------------------------
__global__ __launch_bounds__(256, 2)
void k2_scores(const float* __restrict__ enc, const float* __restrict__ w1,
               const float* __restrict__ v) {
    extern __shared__ __align__(16) float smf[];
    const uint32_t sb = smem_u32(smf);
    float* qs   = smf + (OFF_QS >> 2);
    float* vs   = smf + (OFF_VS >> 2);
    float* sred = smf + (OFF_SR >> 2);

    const int nt = blockIdx.x, n0 = nt * 128;
    const int m0 = blockIdx.y * 128;
    const int b  = m0 / SEQ;
    const int t  = threadIdx.x;
    const int lane = t & 31, w = t >> 5;
    const int wm = w & 1, wn = w >> 1;
    const int g = lane >> 2, c = lane & 3;

    if (t < 128) { qs[t] = g_q[b * ENCD + n0 + t]; vs[t] = v[n0 + t]; }

    // Producer indexing (per-thread invariants).
    // A: chunks f = t and f = t+256; m = f>>2 (0..127), c16 = f&3.
    const int am0 = t >> 2, am1 = am0 + 64, ac = t & 3;
    const float* aS0 = enc + (size_t)(m0 + am0) * ENCD + ac * 4;
    const float* aS1 = enc + (size_t)(m0 + am1) * ENCD + ac * 4;
    const uint32_t aD0 = sb + OFF_A + am0 * 80 + ac * 16;
    const uint32_t aD1 = sb + OFF_A + am1 * 80 + ac * 16;
    // B: chunks f = t and f = t+256; krow = f>>5 (0..15), n16 = f&31.
    const int bk0 = t >> 5, bk1 = bk0 + 8, bn = t & 31;
    const float* bS0 = w1 + (size_t)bk0 * ENCD + n0 + bn * 4;
    const float* bS1 = w1 + (size_t)bk1 * ENCD + n0 + bn * 4;
    const uint32_t bD0 = sb + OFF_B + bk0 * 544 + bn * 16;
    const uint32_t bD1 = sb + OFF_B + bk1 * 544 + bn * 16;

    #define ISSUE(s)                                                         \
        do {                                                                 \
            const uint32_t _ab = ((s) & 3) * ASTG, _bb = ((s) & 3) * BSTG;   \
            CP_ASYNC16(aD0 + _ab, aS0 + (s) * 16);                           \
            CP_ASYNC16(aD1 + _ab, aS1 + (s) * 16);                           \
            CP_ASYNC16(bD0 + _bb, bS0 + (size_t)(s) * 16 * ENCD);            \
            CP_ASYNC16(bD1 + _bb, bS1 + (size_t)(s) * 16 * ENCD);            \
        } while (0)

    float acc[4][4][4];
    #pragma unroll
    for (int mi = 0; mi < 4; mi++)
        #pragma unroll
        for (int ni = 0; ni < 4; ni++)
            #pragma unroll
            for (int r = 0; r < 4; r++) acc[mi][ni][r] = 0.f;

    ISSUE(0); CP_COMMIT();
    ISSUE(1); CP_COMMIT();

    for (int s = 0; s < NSTG; s++) {
        if (s + 2 < NSTG) ISSUE(s + 2);
        CP_COMMIT();                       // empty group near the tail is fine
        CP_WAIT2();                        // oldest (stage s) has landed
        __syncthreads();

        const float* aB = smf + ((s & 3) * ASTG >> 2);
        const float* bB = smf + ((OFF_B + (s & 3) * BSTG) >> 2);
        #pragma unroll
        for (int kk = 0; kk < 16; kk += 8) {
            uint32_t af[4][4], bf[4][2];
            #pragma unroll
            for (int mi = 0; mi < 4; mi++) {
                const int mr = (wm * 64 + mi * 16 + g) * 20;
                af[mi][0] = __float_as_uint(aB[mr + kk + c]);
                af[mi][1] = __float_as_uint(aB[mr + 160 + kk + c]);
                af[mi][2] = __float_as_uint(aB[mr + kk + c + 4]);
                af[mi][3] = __float_as_uint(aB[mr + 160 + kk + c + 4]);
            }
            #pragma unroll
            for (int ni = 0; ni < 4; ni++) {
                const int nb = wn * 32 + ni * 8 + g;
                bf[ni][0] = __float_as_uint(bB[(kk + c) * 136 + nb]);
                bf[ni][1] = __float_as_uint(bB[(kk + c + 4) * 136 + nb]);
            }
            #pragma unroll
            for (int mi = 0; mi < 4; mi++)
                #pragma unroll
                for (int ni = 0; ni < 4; ni++)
                    mma_tf32(acc[mi][ni], af[mi], bf[ni]);
        }
    }

    // Epilogue. C frag: c0=(g,2c), c1=(g,2c+1), c2=(g+8,2c), c3=(g+8,2c+1)
    float rs0[4], rs1[4];
    #pragma unroll
    for (int mi = 0; mi < 4; mi++) {
        float s0 = 0.f, s1 = 0.f;
        #pragma unroll
        for (int ni = 0; ni < 4; ni++) {
            const int n_ = wn * 32 + ni * 8 + c * 2;
            const float q0 = qs[n_], q1 = qs[n_ + 1];
            const float v0 = vs[n_], v1 = vs[n_ + 1];
            s0 += tanh_fast(acc[mi][ni][0] + q0) * v0
                + tanh_fast(acc[mi][ni][1] + q1) * v1;
            s1 += tanh_fast(acc[mi][ni][2] + q0) * v0
                + tanh_fast(acc[mi][ni][3] + q1) * v1;
        }
        s0 += __shfl_xor_sync(0xffffffffu, s0, 1);
        s0 += __shfl_xor_sync(0xffffffffu, s0, 2);
        s1 += __shfl_xor_sync(0xffffffffu, s1, 1);
        s1 += __shfl_xor_sync(0xffffffffu, s1, 2);
        rs0[mi] = s0; rs1[mi] = s1;
    }
    if (c == 0) {
        #pragma unroll
        for (int mi = 0; mi < 4; mi++) {
            sred[wn * 128 + wm * 64 + mi * 16 + g]     = rs0[mi];
            sred[wn * 128 + wm * 64 + mi * 16 + g + 8] = rs1[mi];
        }
    }
    __syncthreads();
    if (t < 128)
        g_partials[(size_t)nt * MTOT + m0 + t] =
            (sred[t] + sred[128 + t]) + (sred[256 + t] + sred[384 + t]);
}

// ---------------------------------------------------------------------------
// K3: sum 8 partials (fixed order), softmax over S per batch.
// ---------------------------------------------------------------------------
__global__ __launch_bounds__(256)
void k3_softmax() {
    __shared__ float red[256];
    const int b = blockIdx.x, t = threadIdx.x;
    float sc[8];
    float mx = -1e30f;
    #pragma unroll
    for (int i = 0; i < 8; i++) {
        const int s = t + 256 * i;
        float v0 = 0.f;
        #pragma unroll
        for (int nt = 0; nt < NTILES; nt++)
            v0 += g_partials[(size_t)nt * MTOT + b * SEQ + s];
        sc[i] = v0;
        mx = fmaxf(mx, v0);
    }
    red[t] = mx; __syncthreads();
    for (int o = 128; o > 0; o >>= 1) {
        if (t < o) red[t] = fmaxf(red[t], red[t + o]);
        __syncthreads();
    }
    mx = red[0]; __syncthreads();
    float sum = 0.f;
    #pragma unroll
    for (int i = 0; i < 8; i++) { sc[i] = expf(sc[i] - mx); sum += sc[i]; }
    red[t] = sum; __syncthreads();
    for (int o = 128; o > 0; o >>= 1) {
        if (t < o) red[t] += red[t + o];
        __syncthreads();
    }
    const float inv = 1.f / red[0];
    #pragma unroll
    for (int i = 0; i < 8; i++)
        g_attn[b * SEQ + t + 256 * i] = sc[i] * inv;
}

// ---------------------------------------------------------------------------
// K4: partial context over S-chunks of 256. grid (4, 32, 8), 256 thr.
// ---------------------------------------------------------------------------
__global__ __launch_bounds__(256)
void k4_context(const float* __restrict__ enc) {
    __shared__ float sat[256];
    const int b  = blockIdx.y;
    const int sc = blockIdx.z;
    const int e  = blockIdx.x * 256 + threadIdx.x;
    const int sbase = sc * 256;
    sat[threadIdx.x] = g_attn[b * SEQ + sbase + threadIdx.x];
    __syncthreads();
    const float* ep = enc + ((size_t)b * SEQ + sbase) * ENCD + e;
    float a0 = 0, a1 = 0, a2 = 0, a3 = 0, a4 = 0, a5 = 0, a6 = 0, a7 = 0;
    for (int s = 0; s < 256; s += 8) {
        a0 += sat[s + 0] * ep[(size_t)(s + 0) * ENCD];
        a1 += sat[s + 1] * ep[(size_t)(s + 1) * ENCD];
        a2 += sat[s + 2] * ep[(size_t)(s + 2) * ENCD];
        a3 += sat[s + 3] * ep[(size_t)(s + 3) * ENCD];
        a4 += sat[s + 4] * ep[(size_t)(s + 4) * ENCD];
        a5 += sat[s + 5] * ep[(size_t)(s + 5) * ENCD];
        a6 += sat[s + 6] * ep[(size_t)(s + 6) * ENCD];
        a7 += sat[s + 7] * ep[(size_t)(s + 7) * ENCD];
    }
    g_ctx[sc][b * ENCD + e] = ((a0 + a1) + (a2 + a3)) + ((a4 + a5) + (a6 + a7));
}

__global__ __launch_bounds__(256)
void k5_reduce(float* __restrict__ out) {
    const int i = blockIdx.x * 256 + threadIdx.x;
    float s = 0.f;
    #pragma unroll
    for (int ch = 0; ch < NCHUNK; ch++) s += g_ctx[ch][i];
    out[i] = s;
}

// ---------------------------------------------------------------------------
extern "C" void kernel_launch(void* const* d_in, const int* in_sizes, int n_in,
                              void* d_out, int out_size) {
    const float* enc = (const float*)d_in[0];
    const float* dec = (const float*)d_in[1];
    const float* w1  = (const float*)d_in[2];
    const float* b1  = (const float*)d_in[3];
    const float* w2  = (const float*)d_in[4];
    const float* b2  = (const float*)d_in[5];
    const float* v   = (const float*)d_in[6];
    float* out = (float*)d_out;

    cudaFuncSetAttribute(k2_scores, cudaFuncAttributeMaxDynamicSharedMemorySize,
                         SMTOT);

    k1_query<<<32, 256>>>(dec, w2, b1, b2);
    k2_scores<<<dim3(NTILES, 512), 256, SMTOT>>>(enc, w1, v);
    k3_softmax<<<32, 256>>>();
    k4_context<<<dim3(4, 32, NCHUNK), 256>>>(enc);
    k5_reduce<<<128, 256>>>(out);
}